// round 15
// baseline (speedup 1.0000x reference)
#include <cuda_runtime.h>
#include <cuda_fp16.h>
#include <cstdint>

#define BATCH 65536
#define HID   4096
#define RDIM  256
#define EDIM  64
#define TOPK  2
#define KTOT  (RDIM + HID)        // 4352
#define NS    (KTOT / 32)         // 136 stages
#define THR   7e-4f
#define MAXFIX 4096
#define KSPL  17                  // 4352 = 17 * 256
#define KCHUNK (KTOT / KSPL)      // 256 (divisible by 16)
#define FROWS 32                  // fixT rows per block
#define NMBLK (BATCH / 128)       // 512 row blocks

// ---------------- device scratch ----------------
__device__ float  g_W[(size_t)KTOT * RDIM];    // fp32 [K][256] (fixup)
__device__ __half g_Wth[(size_t)RDIM * KTOT];  // fp16 [N][K] n-major (main GEMM)
__device__ float  g_c[RDIM];
__device__ float  g_invtau[RDIM];
__device__ float  g_T[(size_t)BATCH * RDIM];
__device__ int    g_cnt;
__device__ int    g_rows[BATCH];
__device__ int    g_flag[NMBLK];
__device__ float  g_part[(size_t)MAXFIX * KSPL * RDIM];

// ---------------- helpers ----------------
__device__ __forceinline__ uint32_t smem_u32(const void* p) {
    uint32_t a;
    asm("{ .reg .u64 t; cvta.to.shared.u64 t, %1; cvt.u32.u64 %0, t; }"
        : "=r"(a) : "l"(p));
    return a;
}
__device__ __forceinline__ uint32_t pack_h2(float lo, float hi) {
    uint32_t r;
    asm("cvt.rn.f16x2.f32 %0, %1, %2;" : "=r"(r) : "f"(hi), "f"(lo));
    return r;
}
__device__ __forceinline__ void mma_f16(float d[4],
                                        uint32_t a0, uint32_t a1, uint32_t a2, uint32_t a3,
                                        uint32_t b0, uint32_t b1) {
    asm volatile(
        "mma.sync.aligned.m16n8k16.row.col.f32.f16.f16.f32 "
        "{%0,%1,%2,%3}, {%4,%5,%6,%7}, {%8,%9}, {%0,%1,%2,%3};"
        : "+f"(d[0]), "+f"(d[1]), "+f"(d[2]), "+f"(d[3])
        : "r"(a0), "r"(a1), "r"(a2), "r"(a3), "r"(b0), "r"(b1));
}
__device__ __forceinline__ float fast_tanh(float x) {
    x = fminf(fmaxf(x, -20.f), 20.f);
    float e = __expf(2.f * x);
    return __fdividef(e - 1.f, e + 1.f);
}
#define CP_ASYNC16(dst, src) \
    asm volatile("cp.async.cg.shared.global [%0], [%1], 16;" :: "r"(dst), "l"(src))
#define CP_COMMIT() asm volatile("cp.async.commit_group;" ::: "memory")
#define CP_WAIT1()  asm volatile("cp.async.wait_group 1;" ::: "memory")

// ---------------- GEMM smem layout (round-13 proven config) ----------------
#define A_ST 36
#define B_STH 40
#define ABUF (128 * A_ST * 4)          // 18432 B
#define BBUF (128 * B_STH * 2)         // 10240 B
#define OFF_A(b) ((b) * ABUF)
#define OFF_B(b) (3 * ABUF + (b) * BBUF)
#define SMEM_GEMM (3 * ABUF + 3 * BBUF)   // 86016 B -> 2 CTAs/SM
#define H_ST 260

// ===========================================================================
// FP16 GEMM + fused epilogue (round-13 measured-best configuration).
// grid = (512, 2): blockIdx.x = 128-row block (fastest), blockIdx.y = n half.
// Second-arriving CTA of each row block runs the epilogue for those 128 rows.
// ===========================================================================
__global__ __launch_bounds__(256, 2)
void gemm_fused(const float* __restrict__ Xh, const float* __restrict__ Xx,
                const __half* __restrict__ Wt, float* __restrict__ C,
                const int* __restrict__ prev_sel, const float* __restrict__ Wg,
                const float* __restrict__ bg, float* __restrict__ out, int B)
{
    extern __shared__ __align__(128) char smem[];
    const uint32_t sb = smem_u32(smem);

    const int tid  = threadIdx.x;
    const int warp = tid >> 5;
    const int lane = tid & 31;
    const int g    = lane >> 2;
    const int tg   = lane & 3;
    const int wm   = (warp >> 2) * 64;
    const int wn   = (warp & 3) * 32;
    const int mb   = blockIdx.x;          // row block (fast)
    const int m0   = mb * 128;
    const int n0   = blockIdx.y * 128;    // n half (slow)

    float d[4][4][4];
#pragma unroll
    for (int mt = 0; mt < 4; mt++)
#pragma unroll
        for (int nt = 0; nt < 4; nt++)
#pragma unroll
            for (int q = 0; q < 4; q++) d[mt][nt][q] = 0.f;

    auto issue = [&](int s) {
        const int k0  = s * 32;
        const int buf = s % 3;
        uint32_t abase = sb + OFF_A(buf);
#pragma unroll
        for (int i = 0; i < 4; i++) {
            int lin = i * 256 + tid;
            int row = lin >> 3;
            int c4  = lin & 7;
            int kg  = k0 + c4 * 4;
            const float* src = (kg < RDIM)
                ? (Xh + (size_t)(m0 + row) * RDIM + kg)
                : (Xx + (size_t)(m0 + row) * HID + (kg - RDIM));
            CP_ASYNC16(abase + (uint32_t)(row * A_ST + c4 * 4) * 4, src);
        }
        uint32_t bbase = sb + OFF_B(buf);
#pragma unroll
        for (int i = 0; i < 2; i++) {
            int lin = i * 256 + tid;
            int nr  = lin >> 2;
            int c8  = lin & 3;
            CP_ASYNC16(bbase + (uint32_t)(nr * B_STH + c8 * 8) * 2,
                       Wt + (size_t)(n0 + nr) * KTOT + k0 + c8 * 8);
        }
        CP_COMMIT();
    };

    auto compute = [&](int buf) {
        const float*  As = (const float*)(smem + OFF_A(buf));
        const __half* Bs = (const __half*)(smem + OFF_B(buf));
#pragma unroll
        for (int k16 = 0; k16 < 2; k16++) {
            const int kk = k16 * 16;
            uint32_t b0[4], b1[4];
#pragma unroll
            for (int nt = 0; nt < 4; nt++) {
                int nb = wn + nt * 8 + g;
                b0[nt] = *reinterpret_cast<const uint32_t*>(&Bs[nb * B_STH + kk + 2 * tg]);
                b1[nt] = *reinterpret_cast<const uint32_t*>(&Bs[nb * B_STH + kk + 2 * tg + 8]);
            }
#pragma unroll
            for (int mt = 0; mt < 4; mt++) {
                int r = (wm + mt * 16 + g) * A_ST + kk + 2 * tg;
                float2 v0 = *reinterpret_cast<const float2*>(&As[r]);
                float2 v1 = *reinterpret_cast<const float2*>(&As[r + 8 * A_ST]);
                float2 v2 = *reinterpret_cast<const float2*>(&As[r + 8]);
                float2 v3 = *reinterpret_cast<const float2*>(&As[r + 8 * A_ST + 8]);
                uint32_t a0 = pack_h2(v0.x, v0.y);
                uint32_t a1 = pack_h2(v1.x, v1.y);
                uint32_t a2 = pack_h2(v2.x, v2.y);
                uint32_t a3 = pack_h2(v3.x, v3.y);
#pragma unroll
                for (int nt = 0; nt < 4; nt++)
                    mma_f16(d[mt][nt], a0, a1, a2, a3, b0[nt], b1[nt]);
            }
        }
    };

    issue(0);
    issue(1);
    for (int s = 0; s < NS; s++) {
        CP_WAIT1();
        __syncthreads();
        if (s + 2 < NS) issue(s + 2); else CP_COMMIT();
        compute(s % 3);
    }

    // ---- writeback T ----
#pragma unroll
    for (int mt = 0; mt < 4; mt++) {
        int r0 = m0 + wm + mt * 16 + g;
#pragma unroll
        for (int nt = 0; nt < 4; nt++) {
            int c0 = n0 + wn + nt * 8 + tg * 2;
            *reinterpret_cast<float2*>(C + (size_t)r0 * 256 + c0) =
                make_float2(d[mt][nt][0], d[mt][nt][1]);
            *reinterpret_cast<float2*>(C + (size_t)(r0 + 8) * 256 + c0) =
                make_float2(d[mt][nt][2], d[mt][nt][3]);
        }
    }

    // ---- arrival: second CTA of this row block runs the epilogue ----
    __threadfence();
    __shared__ int s_old;
    __syncthreads();
    if (tid == 0) s_old = atomicAdd(&g_flag[mb], 1);
    __syncthreads();
    if (s_old == 0) return;
    __threadfence();

    float* sH = (float*)smem;                    // [32][260]
    float* sL = (float*)(smem + 33280);          // [32][64]

#pragma unroll 1
    for (int chunk = 0; chunk < 4; chunk++) {
        const size_t r0 = (size_t)m0 + chunk * 32;
        __syncthreads();
#pragma unroll
        for (int it = 0; it < 8; it++) {
            int lin = it * 256 + tid;
            int row = lin >> 6;
            int c4  = (lin & 63) * 4;
            size_t gbase = (r0 + row) * 256 + c4;
            float4 hv = *reinterpret_cast<const float4*>(Xh + gbase);
            float4 tv = *reinterpret_cast<const float4*>(&g_T[gbase]);
            float4 cv = *reinterpret_cast<const float4*>(&g_c[c4]);
            float4 iv = *reinterpret_cast<const float4*>(&g_invtau[c4]);
            float4 r;
            r.x = hv.x + 0.1f * (-hv.x * iv.x + fast_tanh(tv.x + cv.x));
            r.y = hv.y + 0.1f * (-hv.y * iv.y + fast_tanh(tv.y + cv.y));
            r.z = hv.z + 0.1f * (-hv.z * iv.z + fast_tanh(tv.z + cv.z));
            r.w = hv.w + 0.1f * (-hv.w * iv.w + fast_tanh(tv.w + cv.w));
            *reinterpret_cast<float4*>(&sH[row * H_ST + c4]) = r;
        }
        __syncthreads();
        {
            const int eg = (tid & 15) * 4;
            const int rb = tid >> 4;
            float4 acc0 = make_float4(0.f, 0.f, 0.f, 0.f);
            float4 acc1 = make_float4(0.f, 0.f, 0.f, 0.f);
            const float* h0 = sH + rb * H_ST;
            const float* h1 = sH + (rb + 16) * H_ST;
#pragma unroll 8
            for (int k = 0; k < RDIM; k++) {
                float4 w = __ldg(reinterpret_cast<const float4*>(Wg + k * 64 + eg));
                float a = h0[k], b = h1[k];
                acc0.x = fmaf(a, w.x, acc0.x); acc0.y = fmaf(a, w.y, acc0.y);
                acc0.z = fmaf(a, w.z, acc0.z); acc0.w = fmaf(a, w.w, acc0.w);
                acc1.x = fmaf(b, w.x, acc1.x); acc1.y = fmaf(b, w.y, acc1.y);
                acc1.z = fmaf(b, w.z, acc1.z); acc1.w = fmaf(b, w.w, acc1.w);
            }
            float4 bgv = *reinterpret_cast<const float4*>(bg + eg);
            acc0.x += bgv.x; acc0.y += bgv.y; acc0.z += bgv.z; acc0.w += bgv.w;
            acc1.x += bgv.x; acc1.y += bgv.y; acc1.z += bgv.z; acc1.w += bgv.w;
            *reinterpret_cast<float4*>(&sL[rb * 64 + eg]) = acc0;
            *reinterpret_cast<float4*>(&sL[(rb + 16) * 64 + eg]) = acc1;
        }
        __syncthreads();
        if (tid < 32) {
            int row = tid;
            size_t orow = r0 + row;
            int p0 = prev_sel[orow * 2 + 0];
            int p1 = prev_sel[orow * 2 + 1];
            float v1 = -1e30f, v2 = -1e30f, v3 = -1e30f;
            int i1 = 0, i2 = 0;
#pragma unroll
            for (int q = 0; q < 64; q++) {
                float v = sL[row * 64 + q] + ((q == p0 || q == p1) ? 0.1f : 0.f);
                if (v > v1)      { v3 = v2; v2 = v1; i2 = i1; v1 = v; i1 = q; }
                else if (v > v2) { v3 = v2; v2 = v; i2 = q; }
                else if (v > v3) { v3 = v; }
            }
            float gap = fminf(v1 - v2, v2 - v3);
            if (gap < THR) {
                int slot = atomicAdd(&g_cnt, 1);
                if (slot < BATCH) g_rows[slot] = (int)orow;
            }
            float e2 = expf(v2 - v1);
            float sm = 1.f + e2;
            out[orow * 2 + 0] = (float)i1;
            out[orow * 2 + 1] = (float)i2;
            size_t woff = (size_t)2 * B;
            out[woff + orow * 2 + 0] = 1.f / sm;
            out[woff + orow * 2 + 1] = e2 / sm;
        }
    }
}

// ===========================================================================
// Prep: g_W fp32 + g_Wth fp16 transposed; g_c; g_invtau; zero g_cnt/g_flag.
// ===========================================================================
__global__ __launch_bounds__(256)
void k_prep(const float* __restrict__ Wp, const float* __restrict__ Bm,
            const float* __restrict__ A, const float* __restrict__ bp,
            const float* __restrict__ tau)
{
    __shared__ float sW16[16][257];
    const int tid = threadIdx.x;
    const int kb = blockIdx.x * 16;
    if (blockIdx.x == 0 && tid == 0) g_cnt = 0;
    if (blockIdx.x < NMBLK / 256) g_flag[blockIdx.x * 256 + tid] = 0;

    float vals[16];
    if (kb < RDIM) {
#pragma unroll
        for (int r = 0; r < 16; r++) {
            vals[r] = A[(size_t)(kb + r) * RDIM + tid];
            g_W[(size_t)(kb + r) * RDIM + tid] = vals[r];
        }
    } else {
        const int i0 = kb - RDIM;
#pragma unroll
        for (int r = 0; r < 16; r++)
            sW16[r][tid] = Wp[(size_t)(i0 + r) * RDIM + tid];
        __syncthreads();
#pragma unroll
        for (int r = 0; r < 16; r++) vals[r] = 0.f;
#pragma unroll 4
        for (int k = 0; k < RDIM; k++) {
            float bmv = Bm[k * RDIM + tid];
#pragma unroll
            for (int r = 0; r < 16; r++)
                vals[r] = fmaf(sW16[r][k], bmv, vals[r]);
        }
#pragma unroll
        for (int r = 0; r < 16; r++)
            g_W[(size_t)(kb + r) * RDIM + tid] = vals[r];
    }

    {
        uint32_t p[8];
#pragma unroll
        for (int j = 0; j < 8; j++) {
            uint32_t r;
            asm("cvt.rn.f16x2.f32 %0, %1, %2;" : "=r"(r)
                : "f"(vals[2 * j + 1]), "f"(vals[2 * j]));
            p[j] = r;
        }
        uint4* dst = reinterpret_cast<uint4*>(
            reinterpret_cast<char*>(g_Wth) + ((size_t)tid * KTOT + kb) * 2);
        dst[0] = make_uint4(p[0], p[1], p[2], p[3]);
        dst[1] = make_uint4(p[4], p[5], p[6], p[7]);
    }

    if (blockIdx.x == 0) {
        float c = 0.f;
#pragma unroll 4
        for (int k = 0; k < RDIM; k++)
            c = fmaf(bp[k], Bm[k * RDIM + tid], c);
        g_c[tid] = c;
        g_invtau[tid] = 1.f / tau[tid];
    }
}

// ===========================================================================
// Fixup GEMM, split-K: 32 rows/block x 17 K-splits of 256 (2x parallelism).
// Exact fp32 partials for flagged rows into g_part (deterministic).
// ===========================================================================
__global__ __launch_bounds__(256)
void k_fixT(const float* __restrict__ h, const float* __restrict__ x,
            const float* __restrict__ W)
{
    int nrows = g_cnt; if (nrows > MAXFIX) nrows = MAXFIX;
    const int m0 = blockIdx.x * FROWS;
    if (m0 >= nrows) return;
    const int ks = blockIdx.y;
    const int kbase = ks * KCHUNK;

    __shared__ float sX[FROWS][16];
    __shared__ float sW[16][256];
    __shared__ int   srows[FROWS];

    const int tid = threadIdx.x;
    const int tx = tid & 31, ty = tid >> 5;       // ty 0..7
    const int xr = (tid & 127) >> 2, xq = tid & 3; // rows 0..31, quads 0..3
    const int wr = tid >> 6, wc = tid & 63;

    if (tid < FROWS) {
        int idx = m0 + tid;
        srows[tid] = g_rows[idx < nrows ? idx : nrows - 1];
    }
    __syncthreads();

    float acc[4][8];
#pragma unroll
    for (int i = 0; i < 4; i++)
#pragma unroll
        for (int j = 0; j < 8; j++) acc[i][j] = 0.f;

    for (int k0 = kbase; k0 < kbase + KCHUNK; k0 += 16) {
        if (tid < 128) {
            int row = srows[xr];
            int kg = k0 + xq * 4;
            const float* src = (kg < RDIM)
                ? (h + (size_t)row * RDIM + kg)
                : (x + (size_t)row * HID + (kg - RDIM));
            *reinterpret_cast<float4*>(&sX[xr][xq * 4]) =
                *reinterpret_cast<const float4*>(src);
        }
#pragma unroll
        for (int r = 0; r < 4; r++)
            *reinterpret_cast<float4*>(&sW[wr + 4 * r][wc * 4]) =
                *reinterpret_cast<const float4*>(W + (size_t)(k0 + wr + 4 * r) * 256 + wc * 4);
        __syncthreads();

#pragma unroll
        for (int k = 0; k < 16; k++) {
            float a[4], b[8];
#pragma unroll
            for (int i = 0; i < 4; i++) a[i] = sX[ty + 8 * i][k];
#pragma unroll
            for (int j = 0; j < 8; j++) b[j] = sW[k][tx + 32 * j];
#pragma unroll
            for (int i = 0; i < 4; i++)
#pragma unroll
                for (int j = 0; j < 8; j++)
                    acc[i][j] = fmaf(a[i], b[j], acc[i][j]);
        }
        __syncthreads();
    }

#pragma unroll
    for (int i = 0; i < 4; i++) {
        int rl = ty + 8 * i;
        if (m0 + rl < nrows) {
            float* dst = &g_part[((size_t)(m0 + rl) * KSPL + ks) * RDIM];
#pragma unroll
            for (int j = 0; j < 8; j++)
                dst[tx + 32 * j] = acc[i][j];
        }
    }
}

// ===========================================================================
// Fixup epilogue: reduce K-split partials, exact recompute, overwrite.
// ===========================================================================
__global__ __launch_bounds__(256)
void k_fixEpi(const float* __restrict__ h, const int* __restrict__ prev_sel,
              const float* __restrict__ tau, const float* __restrict__ Wg,
              const float* __restrict__ bg, float* __restrict__ out, int B)
{
    __shared__ float sH[RDIM];
    __shared__ float sPart[4][EDIM];
    __shared__ float sL[EDIM];
    const int j = threadIdx.x;
    int n = g_cnt; if (n > MAXFIX) n = MAXFIX;

    for (int r = blockIdx.x; r < n; r += gridDim.x) {
        size_t row = (size_t)g_rows[r];
        float Tj = 0.f;
#pragma unroll
        for (int ks = 0; ks < KSPL; ks++)
            Tj += g_part[((size_t)r * KSPL + ks) * RDIM + j];
        float hj = h[row * 256 + j];
        sH[j] = hj + 0.1f * (-hj / tau[j] + tanhf(Tj + g_c[j]));
        __syncthreads();

        int e = j & 63, p = j >> 6;
        float acc = 0.f;
#pragma unroll 8
        for (int k = p * 64; k < p * 64 + 64; k++)
            acc = fmaf(sH[k], Wg[k * EDIM + e], acc);
        sPart[p][e] = acc;
        __syncthreads();

        if (j < EDIM) {
            float lg = sPart[0][j] + sPart[1][j] + sPart[2][j] + sPart[3][j] + bg[j];
            int p0 = prev_sel[row * 2 + 0];
            int p1 = prev_sel[row * 2 + 1];
            if (j == p0 || j == p1) lg += 0.1f;
            sL[j] = lg;
        }
        __syncthreads();

        if (j == 0) {
            float v1 = -1e30f, v2 = -1e30f;
            int i1 = 0, i2 = 0;
#pragma unroll
            for (int q = 0; q < 64; q++) {
                float v = sL[q];
                if (v > v1) { v2 = v1; i2 = i1; v1 = v; i1 = q; }
                else if (v > v2) { v2 = v; i2 = q; }
            }
            float e2 = expf(v2 - v1);
            float sm = 1.f + e2;
            out[row * 2 + 0] = (float)i1;
            out[row * 2 + 1] = (float)i2;
            size_t woff = (size_t)2 * B;
            out[woff + row * 2 + 0] = 1.f / sm;
            out[woff + row * 2 + 1] = e2 / sm;
        }
        __syncthreads();
    }
}

// ===========================================================================
extern "C" void kernel_launch(void* const* d_in, const int* in_sizes, int n_in,
                              void* d_out, int out_size)
{
    const float *x = 0, *h = 0, *Wp = 0, *bp = 0, *tau = 0, *A = 0, *Bm = 0,
                *Wg = 0, *bg = 0;
    const int* prev_sel = 0;
    for (int i = 0; i < n_in; i++) {
        int s = in_sizes[i];
        const void* pv = d_in[i];
        switch (s) {
            case BATCH * HID:  x = (const float*)pv; break;
            case BATCH * RDIM: h = (const float*)pv; break;
            case BATCH * TOPK: prev_sel = (const int*)pv; break;
            case HID * RDIM:   Wp = (const float*)pv; break;
            case RDIM:         if (!bp) bp = (const float*)pv; else tau = (const float*)pv; break;
            case RDIM * RDIM:  if (!A) A = (const float*)pv; else Bm = (const float*)pv; break;
            case RDIM * EDIM:  Wg = (const float*)pv; break;
            case EDIM:         bg = (const float*)pv; break;
            default: break;
        }
    }
    if (!x)        x        = (const float*)d_in[0];
    if (!h)        h        = (const float*)d_in[1];
    if (!prev_sel) prev_sel = (const int*)d_in[2];
    if (!Wp)       Wp       = (const float*)d_in[3];
    if (!bp)       bp       = (const float*)d_in[4];
    if (!tau)      tau      = (const float*)d_in[5];
    if (!A)        A        = (const float*)d_in[6];
    if (!Bm)       Bm       = (const float*)d_in[7];
    if (!Wg)       Wg       = (const float*)d_in[8];
    if (!bg)       bg       = (const float*)d_in[9];

    static int attr_done = 0;
    if (!attr_done) {
        cudaFuncSetAttribute(gemm_fused, cudaFuncAttributeMaxDynamicSharedMemorySize, SMEM_GEMM);
        attr_done = 1;
    }

    float  *Wptr = 0, *Tp = 0;
    __half *Wth = 0;
    cudaGetSymbolAddress((void**)&Wptr, g_W);
    cudaGetSymbolAddress((void**)&Wth, g_Wth);
    cudaGetSymbolAddress((void**)&Tp, g_T);
    float* out = (float*)d_out;

    // 1) weights + invtau + counters/flags
    k_prep<<<KTOT / 16, 256>>>(Wp, Bm, A, bp, tau);
    // 2) GEMM + fused epilogue (round-13 proven configuration)
    dim3 grid(BATCH / 128, 2);
    gemm_fused<<<grid, 256, SMEM_GEMM>>>(h, x, Wth, Tp, prev_sel, Wg, bg, out, BATCH);
    // 3) exact fp32 recompute of flagged rows (32 rows/block x 17 K-splits)
    dim3 fgrid(MAXFIX / FROWS, KSPL);
    k_fixT<<<fgrid, 256>>>(h, x, Wptr);
    k_fixEpi<<<2048, 256>>>(h, prev_sel, tau, Wg, bg, out, BATCH);
}

// round 16
// speedup vs baseline: 1.5391x; 1.5391x over previous
#include <cuda_runtime.h>
#include <cuda_fp16.h>
#include <cstdint>

#define BATCH 65536
#define HID   4096
#define RDIM  256
#define EDIM  64
#define TOPK  2
#define KTOT  (RDIM + HID)        // 4352
#define NS    (KTOT / 32)         // 136 stages
#define THR   7e-4f
#define MAXFIX 4096
#define KSPL  16
#define KCHUNK (KTOT / KSPL)      // 272
#define NMBLK (BATCH / 128)       // 512 row blocks

// ---------------- device scratch ----------------
__device__ float  g_W[(size_t)KTOT * RDIM];    // fp32 [K][256] (fixup)
__device__ __half g_Wth[(size_t)RDIM * KTOT];  // fp16 [N][K] n-major (main GEMM)
__device__ float  g_c[RDIM];
__device__ float  g_invtau[RDIM];
__device__ float  g_T[(size_t)BATCH * RDIM];
__device__ int    g_cnt;
__device__ int    g_rows[BATCH];
__device__ int    g_flag[NMBLK];               // per row-block arrival counter
__device__ float  g_part[(size_t)MAXFIX * KSPL * RDIM];

// ---------------- helpers ----------------
__device__ __forceinline__ uint32_t smem_u32(const void* p) {
    uint32_t a;
    asm("{ .reg .u64 t; cvta.to.shared.u64 t, %1; cvt.u32.u64 %0, t; }"
        : "=r"(a) : "l"(p));
    return a;
}
__device__ __forceinline__ uint32_t pack_h2(float lo, float hi) {
    uint32_t r;
    asm("cvt.rn.f16x2.f32 %0, %1, %2;" : "=r"(r) : "f"(hi), "f"(lo));
    return r;
}
__device__ __forceinline__ void mma_f16(float d[4],
                                        uint32_t a0, uint32_t a1, uint32_t a2, uint32_t a3,
                                        uint32_t b0, uint32_t b1) {
    asm volatile(
        "mma.sync.aligned.m16n8k16.row.col.f32.f16.f16.f32 "
        "{%0,%1,%2,%3}, {%4,%5,%6,%7}, {%8,%9}, {%0,%1,%2,%3};"
        : "+f"(d[0]), "+f"(d[1]), "+f"(d[2]), "+f"(d[3])
        : "r"(a0), "r"(a1), "r"(a2), "r"(a3), "r"(b0), "r"(b1));
}
__device__ __forceinline__ float fast_tanh(float x) {
    x = fminf(fmaxf(x, -20.f), 20.f);
    float e = __expf(2.f * x);
    return __fdividef(e - 1.f, e + 1.f);
}
#define CP_ASYNC16(dst, src) \
    asm volatile("cp.async.cg.shared.global [%0], [%1], 16;" :: "r"(dst), "l"(src))
#define CP_COMMIT() asm volatile("cp.async.commit_group;" ::: "memory")
#define CP_WAIT1()  asm volatile("cp.async.wait_group 1;" ::: "memory")

// ---------------- GEMM smem layout ----------------
#define A_ST 36
#define B_STH 40
#define ABUF (128 * A_ST * 4)          // 18432 B
#define BBUF (128 * B_STH * 2)         // 10240 B
#define OFF_A(b) ((b) * ABUF)
#define OFF_B(b) (3 * ABUF + (b) * BBUF)
#define SMEM_GEMM (3 * ABUF + 3 * BBUF)   // 86016 B -> 2 CTAs/SM
#define H_ST 260

// ===========================================================================
// FP16 GEMM + fused epilogue (measured-best configuration, rounds 11/13).
// grid = (512, 2): blockIdx.x = 128-row block (fastest), blockIdx.y = n half.
// Second-arriving CTA of each row block runs the epilogue for those 128 rows.
// ===========================================================================
__global__ __launch_bounds__(256, 2)
void gemm_fused(const float* __restrict__ Xh, const float* __restrict__ Xx,
                const __half* __restrict__ Wt, float* __restrict__ C,
                const int* __restrict__ prev_sel, const float* __restrict__ Wg,
                const float* __restrict__ bg, float* __restrict__ out, int B)
{
    extern __shared__ __align__(128) char smem[];
    const uint32_t sb = smem_u32(smem);

    const int tid  = threadIdx.x;
    const int warp = tid >> 5;
    const int lane = tid & 31;
    const int g    = lane >> 2;
    const int tg   = lane & 3;
    const int wm   = (warp >> 2) * 64;
    const int wn   = (warp & 3) * 32;
    const int mb   = blockIdx.x;          // row block (fast)
    const int m0   = mb * 128;
    const int n0   = blockIdx.y * 128;    // n half (slow)

    float d[4][4][4];
#pragma unroll
    for (int mt = 0; mt < 4; mt++)
#pragma unroll
        for (int nt = 0; nt < 4; nt++)
#pragma unroll
            for (int q = 0; q < 4; q++) d[mt][nt][q] = 0.f;

    auto issue = [&](int s) {
        const int k0  = s * 32;
        const int buf = s % 3;
        uint32_t abase = sb + OFF_A(buf);
#pragma unroll
        for (int i = 0; i < 4; i++) {
            int lin = i * 256 + tid;
            int row = lin >> 3;
            int c4  = lin & 7;
            int kg  = k0 + c4 * 4;
            const float* src = (kg < RDIM)
                ? (Xh + (size_t)(m0 + row) * RDIM + kg)
                : (Xx + (size_t)(m0 + row) * HID + (kg - RDIM));
            CP_ASYNC16(abase + (uint32_t)(row * A_ST + c4 * 4) * 4, src);
        }
        uint32_t bbase = sb + OFF_B(buf);
#pragma unroll
        for (int i = 0; i < 2; i++) {
            int lin = i * 256 + tid;
            int nr  = lin >> 2;
            int c8  = lin & 3;
            CP_ASYNC16(bbase + (uint32_t)(nr * B_STH + c8 * 8) * 2,
                       Wt + (size_t)(n0 + nr) * KTOT + k0 + c8 * 8);
        }
        CP_COMMIT();
    };

    auto compute = [&](int buf) {
        const float*  As = (const float*)(smem + OFF_A(buf));
        const __half* Bs = (const __half*)(smem + OFF_B(buf));
#pragma unroll
        for (int k16 = 0; k16 < 2; k16++) {
            const int kk = k16 * 16;
            uint32_t b0[4], b1[4];
#pragma unroll
            for (int nt = 0; nt < 4; nt++) {
                int nb = wn + nt * 8 + g;
                b0[nt] = *reinterpret_cast<const uint32_t*>(&Bs[nb * B_STH + kk + 2 * tg]);
                b1[nt] = *reinterpret_cast<const uint32_t*>(&Bs[nb * B_STH + kk + 2 * tg + 8]);
            }
#pragma unroll
            for (int mt = 0; mt < 4; mt++) {
                int r = (wm + mt * 16 + g) * A_ST + kk + 2 * tg;
                float2 v0 = *reinterpret_cast<const float2*>(&As[r]);
                float2 v1 = *reinterpret_cast<const float2*>(&As[r + 8 * A_ST]);
                float2 v2 = *reinterpret_cast<const float2*>(&As[r + 8]);
                float2 v3 = *reinterpret_cast<const float2*>(&As[r + 8 * A_ST + 8]);
                uint32_t a0 = pack_h2(v0.x, v0.y);
                uint32_t a1 = pack_h2(v1.x, v1.y);
                uint32_t a2 = pack_h2(v2.x, v2.y);
                uint32_t a3 = pack_h2(v3.x, v3.y);
#pragma unroll
                for (int nt = 0; nt < 4; nt++)
                    mma_f16(d[mt][nt], a0, a1, a2, a3, b0[nt], b1[nt]);
            }
        }
    };

    issue(0);
    issue(1);
    for (int s = 0; s < NS; s++) {
        CP_WAIT1();
        __syncthreads();
        if (s + 2 < NS) issue(s + 2); else CP_COMMIT();
        compute(s % 3);
    }

    // ---- writeback T ----
#pragma unroll
    for (int mt = 0; mt < 4; mt++) {
        int r0 = m0 + wm + mt * 16 + g;
#pragma unroll
        for (int nt = 0; nt < 4; nt++) {
            int c0 = n0 + wn + nt * 8 + tg * 2;
            *reinterpret_cast<float2*>(C + (size_t)r0 * 256 + c0) =
                make_float2(d[mt][nt][0], d[mt][nt][1]);
            *reinterpret_cast<float2*>(C + (size_t)(r0 + 8) * 256 + c0) =
                make_float2(d[mt][nt][2], d[mt][nt][3]);
        }
    }

    // ---- arrival: second CTA of this row block runs the epilogue ----
    __threadfence();
    __shared__ int s_old;
    __syncthreads();
    if (tid == 0) s_old = atomicAdd(&g_flag[mb], 1);
    __syncthreads();
    if (s_old == 0) return;
    __threadfence();

    float* sH = (float*)smem;                    // [32][260]
    float* sL = (float*)(smem + 33280);          // [32][64]

#pragma unroll 1
    for (int chunk = 0; chunk < 4; chunk++) {
        const size_t r0 = (size_t)m0 + chunk * 32;
        __syncthreads();
#pragma unroll
        for (int it = 0; it < 8; it++) {
            int lin = it * 256 + tid;
            int row = lin >> 6;
            int c4  = (lin & 63) * 4;
            size_t gbase = (r0 + row) * 256 + c4;
            float4 hv = *reinterpret_cast<const float4*>(Xh + gbase);
            float4 tv = *reinterpret_cast<const float4*>(&g_T[gbase]);
            float4 cv = *reinterpret_cast<const float4*>(&g_c[c4]);
            float4 iv = *reinterpret_cast<const float4*>(&g_invtau[c4]);
            float4 r;
            r.x = hv.x + 0.1f * (-hv.x * iv.x + fast_tanh(tv.x + cv.x));
            r.y = hv.y + 0.1f * (-hv.y * iv.y + fast_tanh(tv.y + cv.y));
            r.z = hv.z + 0.1f * (-hv.z * iv.z + fast_tanh(tv.z + cv.z));
            r.w = hv.w + 0.1f * (-hv.w * iv.w + fast_tanh(tv.w + cv.w));
            *reinterpret_cast<float4*>(&sH[row * H_ST + c4]) = r;
        }
        __syncthreads();
        {
            const int eg = (tid & 15) * 4;
            const int rb = tid >> 4;
            float4 acc0 = make_float4(0.f, 0.f, 0.f, 0.f);
            float4 acc1 = make_float4(0.f, 0.f, 0.f, 0.f);
            const float* h0 = sH + rb * H_ST;
            const float* h1 = sH + (rb + 16) * H_ST;
#pragma unroll 8
            for (int k = 0; k < RDIM; k++) {
                float4 w = __ldg(reinterpret_cast<const float4*>(Wg + k * 64 + eg));
                float a = h0[k], b = h1[k];
                acc0.x = fmaf(a, w.x, acc0.x); acc0.y = fmaf(a, w.y, acc0.y);
                acc0.z = fmaf(a, w.z, acc0.z); acc0.w = fmaf(a, w.w, acc0.w);
                acc1.x = fmaf(b, w.x, acc1.x); acc1.y = fmaf(b, w.y, acc1.y);
                acc1.z = fmaf(b, w.z, acc1.z); acc1.w = fmaf(b, w.w, acc1.w);
            }
            float4 bgv = *reinterpret_cast<const float4*>(bg + eg);
            acc0.x += bgv.x; acc0.y += bgv.y; acc0.z += bgv.z; acc0.w += bgv.w;
            acc1.x += bgv.x; acc1.y += bgv.y; acc1.z += bgv.z; acc1.w += bgv.w;
            *reinterpret_cast<float4*>(&sL[rb * 64 + eg]) = acc0;
            *reinterpret_cast<float4*>(&sL[(rb + 16) * 64 + eg]) = acc1;
        }
        __syncthreads();
        if (tid < 32) {
            int row = tid;
            size_t orow = r0 + row;
            int p0 = prev_sel[orow * 2 + 0];
            int p1 = prev_sel[orow * 2 + 1];
            float v1 = -1e30f, v2 = -1e30f, v3 = -1e30f;
            int i1 = 0, i2 = 0;
#pragma unroll
            for (int q = 0; q < 64; q++) {
                float v = sL[row * 64 + q] + ((q == p0 || q == p1) ? 0.1f : 0.f);
                if (v > v1)      { v3 = v2; v2 = v1; i2 = i1; v1 = v; i1 = q; }
                else if (v > v2) { v3 = v2; v2 = v; i2 = q; }
                else if (v > v3) { v3 = v; }
            }
            float gap = fminf(v1 - v2, v2 - v3);
            if (gap < THR) {
                int slot = atomicAdd(&g_cnt, 1);
                if (slot < BATCH) g_rows[slot] = (int)orow;
            }
            float e2 = expf(v2 - v1);
            float sm = 1.f + e2;
            out[orow * 2 + 0] = (float)i1;
            out[orow * 2 + 1] = (float)i2;
            size_t woff = (size_t)2 * B;
            out[woff + orow * 2 + 0] = 1.f / sm;
            out[woff + orow * 2 + 1] = e2 / sm;
        }
    }
}

// ===========================================================================
// Prep: g_W fp32 + g_Wth fp16 transposed; g_c; g_invtau; zero g_cnt/g_flag.
// ===========================================================================
__global__ __launch_bounds__(256)
void k_prep(const float* __restrict__ Wp, const float* __restrict__ Bm,
            const float* __restrict__ A, const float* __restrict__ bp,
            const float* __restrict__ tau)
{
    __shared__ float sW16[16][257];
    const int tid = threadIdx.x;
    const int kb = blockIdx.x * 16;
    if (blockIdx.x == 0 && tid == 0) g_cnt = 0;
    if (blockIdx.x < NMBLK / 256) g_flag[blockIdx.x * 256 + tid] = 0;

    float vals[16];
    if (kb < RDIM) {
#pragma unroll
        for (int r = 0; r < 16; r++) {
            vals[r] = A[(size_t)(kb + r) * RDIM + tid];
            g_W[(size_t)(kb + r) * RDIM + tid] = vals[r];
        }
    } else {
        const int i0 = kb - RDIM;
#pragma unroll
        for (int r = 0; r < 16; r++)
            sW16[r][tid] = Wp[(size_t)(i0 + r) * RDIM + tid];
        __syncthreads();
#pragma unroll
        for (int r = 0; r < 16; r++) vals[r] = 0.f;
#pragma unroll 4
        for (int k = 0; k < RDIM; k++) {
            float bmv = Bm[k * RDIM + tid];
#pragma unroll
            for (int r = 0; r < 16; r++)
                vals[r] = fmaf(sW16[r][k], bmv, vals[r]);
        }
#pragma unroll
        for (int r = 0; r < 16; r++)
            g_W[(size_t)(kb + r) * RDIM + tid] = vals[r];
    }

    {
        uint32_t p[8];
#pragma unroll
        for (int j = 0; j < 8; j++) {
            uint32_t r;
            asm("cvt.rn.f16x2.f32 %0, %1, %2;" : "=r"(r)
                : "f"(vals[2 * j + 1]), "f"(vals[2 * j]));
            p[j] = r;
        }
        uint4* dst = reinterpret_cast<uint4*>(
            reinterpret_cast<char*>(g_Wth) + ((size_t)tid * KTOT + kb) * 2);
        dst[0] = make_uint4(p[0], p[1], p[2], p[3]);
        dst[1] = make_uint4(p[4], p[5], p[6], p[7]);
    }

    if (blockIdx.x == 0) {
        float c = 0.f;
#pragma unroll 4
        for (int k = 0; k < RDIM; k++)
            c = fmaf(bp[k], Bm[k * RDIM + tid], c);
        g_c[tid] = c;
        g_invtau[tid] = 1.f / tau[tid];
    }
}

// ===========================================================================
// Fixup GEMM, split-K (round-13 geometry): 64 rows/block x 16 K-splits.
// Exact fp32 partials for flagged rows into g_part (deterministic).
// ===========================================================================
__global__ __launch_bounds__(256)
void k_fixT(const float* __restrict__ h, const float* __restrict__ x,
            const float* __restrict__ W)
{
    int nrows = g_cnt; if (nrows > MAXFIX) nrows = MAXFIX;
    const int m0 = blockIdx.x * 64;
    if (m0 >= nrows) return;
    const int ks = blockIdx.y;
    const int kbase = ks * KCHUNK;

    __shared__ float sX[64][16];
    __shared__ float sW[16][256];
    __shared__ int   srows[64];

    const int tid = threadIdx.x;
    const int tx = tid & 31, ty = tid >> 5;
    const int xr = tid >> 2, xq = tid & 3;
    const int wr = tid >> 6, wc = tid & 63;

    if (tid < 64) {
        int idx = m0 + tid;
        srows[tid] = g_rows[idx < nrows ? idx : nrows - 1];
    }
    __syncthreads();

    float acc[8][8];
#pragma unroll
    for (int i = 0; i < 8; i++)
#pragma unroll
        for (int j = 0; j < 8; j++) acc[i][j] = 0.f;

    for (int k0 = kbase; k0 < kbase + KCHUNK; k0 += 16) {
        {
            int row = srows[xr];
            int kg = k0 + xq * 4;
            const float* src = (kg < RDIM)
                ? (h + (size_t)row * RDIM + kg)
                : (x + (size_t)row * HID + (kg - RDIM));
            *reinterpret_cast<float4*>(&sX[xr][xq * 4]) =
                *reinterpret_cast<const float4*>(src);
        }
#pragma unroll
        for (int r = 0; r < 4; r++)
            *reinterpret_cast<float4*>(&sW[wr + 4 * r][wc * 4]) =
                *reinterpret_cast<const float4*>(W + (size_t)(k0 + wr + 4 * r) * 256 + wc * 4);
        __syncthreads();

#pragma unroll
        for (int k = 0; k < 16; k++) {
            float a[8], b[8];
#pragma unroll
            for (int i = 0; i < 8; i++) a[i] = sX[ty + 8 * i][k];
#pragma unroll
            for (int j = 0; j < 8; j++) b[j] = sW[k][tx + 32 * j];
#pragma unroll
            for (int i = 0; i < 8; i++)
#pragma unroll
                for (int j = 0; j < 8; j++)
                    acc[i][j] = fmaf(a[i], b[j], acc[i][j]);
        }
        __syncthreads();
    }

#pragma unroll
    for (int i = 0; i < 8; i++) {
        int rl = ty + 8 * i;
        if (m0 + rl < nrows) {
            float* dst = &g_part[((size_t)(m0 + rl) * KSPL + ks) * RDIM];
#pragma unroll
            for (int j = 0; j < 8; j++)
                dst[tx + 32 * j] = acc[i][j];
        }
    }
}

// ===========================================================================
// Fixup epilogue: reduce K-split partials, exact recompute, overwrite.
// ===========================================================================
__global__ __launch_bounds__(256)
void k_fixEpi(const float* __restrict__ h, const int* __restrict__ prev_sel,
              const float* __restrict__ tau, const float* __restrict__ Wg,
              const float* __restrict__ bg, float* __restrict__ out, int B)
{
    __shared__ float sH[RDIM];
    __shared__ float sPart[4][EDIM];
    __shared__ float sL[EDIM];
    const int j = threadIdx.x;
    int n = g_cnt; if (n > MAXFIX) n = MAXFIX;

    for (int r = blockIdx.x; r < n; r += gridDim.x) {
        size_t row = (size_t)g_rows[r];
        float Tj = 0.f;
#pragma unroll
        for (int ks = 0; ks < KSPL; ks++)
            Tj += g_part[((size_t)r * KSPL + ks) * RDIM + j];
        float hj = h[row * 256 + j];
        sH[j] = hj + 0.1f * (-hj / tau[j] + tanhf(Tj + g_c[j]));
        __syncthreads();

        int e = j & 63, p = j >> 6;
        float acc = 0.f;
#pragma unroll 8
        for (int k = p * 64; k < p * 64 + 64; k++)
            acc = fmaf(sH[k], Wg[k * EDIM + e], acc);
        sPart[p][e] = acc;
        __syncthreads();

        if (j < EDIM) {
            float lg = sPart[0][j] + sPart[1][j] + sPart[2][j] + sPart[3][j] + bg[j];
            int p0 = prev_sel[row * 2 + 0];
            int p1 = prev_sel[row * 2 + 1];
            if (j == p0 || j == p1) lg += 0.1f;
            sL[j] = lg;
        }
        __syncthreads();

        if (j == 0) {
            float v1 = -1e30f, v2 = -1e30f;
            int i1 = 0, i2 = 0;
#pragma unroll
            for (int q = 0; q < 64; q++) {
                float v = sL[q];
                if (v > v1) { v2 = v1; i2 = i1; v1 = v; i1 = q; }
                else if (v > v2) { v2 = v; i2 = q; }
            }
            float e2 = expf(v2 - v1);
            float sm = 1.f + e2;
            out[row * 2 + 0] = (float)i1;
            out[row * 2 + 1] = (float)i2;
            size_t woff = (size_t)2 * B;
            out[woff + row * 2 + 0] = 1.f / sm;
            out[woff + row * 2 + 1] = e2 / sm;
        }
        __syncthreads();
    }
}

// ===========================================================================
extern "C" void kernel_launch(void* const* d_in, const int* in_sizes, int n_in,
                              void* d_out, int out_size)
{
    const float *x = 0, *h = 0, *Wp = 0, *bp = 0, *tau = 0, *A = 0, *Bm = 0,
                *Wg = 0, *bg = 0;
    const int* prev_sel = 0;
    for (int i = 0; i < n_in; i++) {
        int s = in_sizes[i];
        const void* pv = d_in[i];
        switch (s) {
            case BATCH * HID:  x = (const float*)pv; break;
            case BATCH * RDIM: h = (const float*)pv; break;
            case BATCH * TOPK: prev_sel = (const int*)pv; break;
            case HID * RDIM:   Wp = (const float*)pv; break;
            case RDIM:         if (!bp) bp = (const float*)pv; else tau = (const float*)pv; break;
            case RDIM * RDIM:  if (!A) A = (const float*)pv; else Bm = (const float*)pv; break;
            case RDIM * EDIM:  Wg = (const float*)pv; break;
            case EDIM:         bg = (const float*)pv; break;
            default: break;
        }
    }
    if (!x)        x        = (const float*)d_in[0];
    if (!h)        h        = (const float*)d_in[1];
    if (!prev_sel) prev_sel = (const int*)d_in[2];
    if (!Wp)       Wp       = (const float*)d_in[3];
    if (!bp)       bp       = (const float*)d_in[4];
    if (!tau)      tau      = (const float*)d_in[5];
    if (!A)        A        = (const float*)d_in[6];
    if (!Bm)       Bm       = (const float*)d_in[7];
    if (!Wg)       Wg       = (const float*)d_in[8];
    if (!bg)       bg       = (const float*)d_in[9];

    static int attr_done = 0;
    if (!attr_done) {
        cudaFuncSetAttribute(gemm_fused, cudaFuncAttributeMaxDynamicSharedMemorySize, SMEM_GEMM);
        attr_done = 1;
    }

    float  *Wptr = 0, *Tp = 0;
    __half *Wth = 0;
    cudaGetSymbolAddress((void**)&Wptr, g_W);
    cudaGetSymbolAddress((void**)&Wth, g_Wth);
    cudaGetSymbolAddress((void**)&Tp, g_T);
    float* out = (float*)d_out;

    // 1) weights + invtau + counters/flags
    k_prep<<<KTOT / 16, 256>>>(Wp, Bm, A, bp, tau);
    // 2) GEMM + fused epilogue (measured-best configuration)
    dim3 grid(BATCH / 128, 2);
    gemm_fused<<<grid, 256, SMEM_GEMM>>>(h, x, Wth, Tp, prev_sel, Wg, bg, out, BATCH);
    // 3) exact fp32 recompute of flagged rows (64 rows/block x 16 K-splits)
    dim3 fgrid(MAXFIX / 64, KSPL);
    k_fixT<<<fgrid, 256>>>(h, x, Wptr);
    k_fixEpi<<<2048, 256>>>(h, prev_sel, tau, Wg, bg, out, BATCH);
}

// round 17
// speedup vs baseline: 1.5529x; 1.0090x over previous
#include <cuda_runtime.h>
#include <cuda_fp16.h>
#include <cstdint>

#define BATCH 65536
#define HID   4096
#define RDIM  256
#define EDIM  64
#define TOPK  2
#define KTOT  (RDIM + HID)        // 4352
#define NS    (KTOT / 32)         // 136 stages
#define THR   7e-4f
#define MAXFIX 4096
#define KSPL  16
#define KCHUNK (KTOT / KSPL)      // 272
#define NMBLK (BATCH / 128)       // 512 row blocks

// ---------------- device scratch ----------------
__device__ float  g_W[(size_t)KTOT * RDIM];    // fp32 [K][256] (fixup)
__device__ __half g_Wth[(size_t)RDIM * KTOT];  // fp16 [N][K] n-major (main GEMM)
__device__ float  g_c[RDIM];
__device__ float  g_invtau[RDIM];
__device__ float  g_T[(size_t)BATCH * RDIM];
__device__ int    g_cnt;
__device__ int    g_rows[BATCH];
__device__ int    g_flag[NMBLK];               // per row-block arrival counter
__device__ float  g_part[(size_t)MAXFIX * KSPL * RDIM];

// ---------------- helpers ----------------
__device__ __forceinline__ uint32_t smem_u32(const void* p) {
    uint32_t a;
    asm("{ .reg .u64 t; cvta.to.shared.u64 t, %1; cvt.u32.u64 %0, t; }"
        : "=r"(a) : "l"(p));
    return a;
}
__device__ __forceinline__ uint32_t pack_h2(float lo, float hi) {
    uint32_t r;
    asm("cvt.rn.f16x2.f32 %0, %1, %2;" : "=r"(r) : "f"(hi), "f"(lo));
    return r;
}
__device__ __forceinline__ void mma_f16(float d[4],
                                        uint32_t a0, uint32_t a1, uint32_t a2, uint32_t a3,
                                        uint32_t b0, uint32_t b1) {
    asm volatile(
        "mma.sync.aligned.m16n8k16.row.col.f32.f16.f16.f32 "
        "{%0,%1,%2,%3}, {%4,%5,%6,%7}, {%8,%9}, {%0,%1,%2,%3};"
        : "+f"(d[0]), "+f"(d[1]), "+f"(d[2]), "+f"(d[3])
        : "r"(a0), "r"(a1), "r"(a2), "r"(a3), "r"(b0), "r"(b1));
}
__device__ __forceinline__ float fast_tanh(float x) {
    x = fminf(fmaxf(x, -20.f), 20.f);
    float e = __expf(2.f * x);
    return __fdividef(e - 1.f, e + 1.f);
}
#define CP_ASYNC16(dst, src) \
    asm volatile("cp.async.cg.shared.global [%0], [%1], 16;" :: "r"(dst), "l"(src))
#define CP_COMMIT() asm volatile("cp.async.commit_group;" ::: "memory")
#define CP_WAIT1()  asm volatile("cp.async.wait_group 1;" ::: "memory")

// ---------------- GEMM smem layout ----------------
#define A_ST 36
#define B_STH 40
#define ABUF (128 * A_ST * 4)          // 18432 B
#define BBUF (128 * B_STH * 2)         // 10240 B
#define OFF_A(b) ((b) * ABUF)
#define OFF_B(b) (3 * ABUF + (b) * BBUF)
#define SMEM_GEMM (3 * ABUF + 3 * BBUF)   // 86016 B -> 2 CTAs/SM
#define H_ST 260

// ===========================================================================
// FP16 GEMM + fused epilogue (measured-best configuration, rounds 11/13/16).
// grid = (512, 2): blockIdx.x = 128-row block (fastest), blockIdx.y = n half.
// Second-arriving CTA of each row block runs the epilogue for those 128 rows.
// ===========================================================================
__global__ __launch_bounds__(256, 2)
void gemm_fused(const float* __restrict__ Xh, const float* __restrict__ Xx,
                const __half* __restrict__ Wt, float* __restrict__ C,
                const int* __restrict__ prev_sel, const float* __restrict__ Wg,
                const float* __restrict__ bg, float* __restrict__ out, int B)
{
    extern __shared__ __align__(128) char smem[];
    const uint32_t sb = smem_u32(smem);

    const int tid  = threadIdx.x;
    const int warp = tid >> 5;
    const int lane = tid & 31;
    const int g    = lane >> 2;
    const int tg   = lane & 3;
    const int wm   = (warp >> 2) * 64;
    const int wn   = (warp & 3) * 32;
    const int mb   = blockIdx.x;          // row block (fast)
    const int m0   = mb * 128;
    const int n0   = blockIdx.y * 128;    // n half (slow)

    float d[4][4][4];
#pragma unroll
    for (int mt = 0; mt < 4; mt++)
#pragma unroll
        for (int nt = 0; nt < 4; nt++)
#pragma unroll
            for (int q = 0; q < 4; q++) d[mt][nt][q] = 0.f;

    auto issue = [&](int s) {
        const int k0  = s * 32;
        const int buf = s % 3;
        uint32_t abase = sb + OFF_A(buf);
#pragma unroll
        for (int i = 0; i < 4; i++) {
            int lin = i * 256 + tid;
            int row = lin >> 3;
            int c4  = lin & 7;
            int kg  = k0 + c4 * 4;
            const float* src = (kg < RDIM)
                ? (Xh + (size_t)(m0 + row) * RDIM + kg)
                : (Xx + (size_t)(m0 + row) * HID + (kg - RDIM));
            CP_ASYNC16(abase + (uint32_t)(row * A_ST + c4 * 4) * 4, src);
        }
        uint32_t bbase = sb + OFF_B(buf);
#pragma unroll
        for (int i = 0; i < 2; i++) {
            int lin = i * 256 + tid;
            int nr  = lin >> 2;
            int c8  = lin & 3;
            CP_ASYNC16(bbase + (uint32_t)(nr * B_STH + c8 * 8) * 2,
                       Wt + (size_t)(n0 + nr) * KTOT + k0 + c8 * 8);
        }
        CP_COMMIT();
    };

    auto compute = [&](int buf) {
        const float*  As = (const float*)(smem + OFF_A(buf));
        const __half* Bs = (const __half*)(smem + OFF_B(buf));
#pragma unroll
        for (int k16 = 0; k16 < 2; k16++) {
            const int kk = k16 * 16;
            uint32_t b0[4], b1[4];
#pragma unroll
            for (int nt = 0; nt < 4; nt++) {
                int nb = wn + nt * 8 + g;
                b0[nt] = *reinterpret_cast<const uint32_t*>(&Bs[nb * B_STH + kk + 2 * tg]);
                b1[nt] = *reinterpret_cast<const uint32_t*>(&Bs[nb * B_STH + kk + 2 * tg + 8]);
            }
#pragma unroll
            for (int mt = 0; mt < 4; mt++) {
                int r = (wm + mt * 16 + g) * A_ST + kk + 2 * tg;
                float2 v0 = *reinterpret_cast<const float2*>(&As[r]);
                float2 v1 = *reinterpret_cast<const float2*>(&As[r + 8 * A_ST]);
                float2 v2 = *reinterpret_cast<const float2*>(&As[r + 8]);
                float2 v3 = *reinterpret_cast<const float2*>(&As[r + 8 * A_ST + 8]);
                uint32_t a0 = pack_h2(v0.x, v0.y);
                uint32_t a1 = pack_h2(v1.x, v1.y);
                uint32_t a2 = pack_h2(v2.x, v2.y);
                uint32_t a3 = pack_h2(v3.x, v3.y);
#pragma unroll
                for (int nt = 0; nt < 4; nt++)
                    mma_f16(d[mt][nt], a0, a1, a2, a3, b0[nt], b1[nt]);
            }
        }
    };

    issue(0);
    issue(1);
    for (int s = 0; s < NS; s++) {
        CP_WAIT1();
        __syncthreads();
        if (s + 2 < NS) issue(s + 2); else CP_COMMIT();
        compute(s % 3);
    }

    // ---- writeback T ----
#pragma unroll
    for (int mt = 0; mt < 4; mt++) {
        int r0 = m0 + wm + mt * 16 + g;
#pragma unroll
        for (int nt = 0; nt < 4; nt++) {
            int c0 = n0 + wn + nt * 8 + tg * 2;
            *reinterpret_cast<float2*>(C + (size_t)r0 * 256 + c0) =
                make_float2(d[mt][nt][0], d[mt][nt][1]);
            *reinterpret_cast<float2*>(C + (size_t)(r0 + 8) * 256 + c0) =
                make_float2(d[mt][nt][2], d[mt][nt][3]);
        }
    }

    // ---- arrival: second CTA of this row block runs the epilogue ----
    __threadfence();
    __shared__ int s_old;
    __syncthreads();
    if (tid == 0) s_old = atomicAdd(&g_flag[mb], 1);
    __syncthreads();
    if (s_old == 0) return;
    __threadfence();

    float* sH = (float*)smem;                    // [32][260]
    float* sL = (float*)(smem + 33280);          // [32][64]

#pragma unroll 1
    for (int chunk = 0; chunk < 4; chunk++) {
        const size_t r0 = (size_t)m0 + chunk * 32;
        __syncthreads();
#pragma unroll
        for (int it = 0; it < 8; it++) {
            int lin = it * 256 + tid;
            int row = lin >> 6;
            int c4  = (lin & 63) * 4;
            size_t gbase = (r0 + row) * 256 + c4;
            float4 hv = *reinterpret_cast<const float4*>(Xh + gbase);
            float4 tv = *reinterpret_cast<const float4*>(&g_T[gbase]);
            float4 cv = *reinterpret_cast<const float4*>(&g_c[c4]);
            float4 iv = *reinterpret_cast<const float4*>(&g_invtau[c4]);
            float4 r;
            r.x = hv.x + 0.1f * (-hv.x * iv.x + fast_tanh(tv.x + cv.x));
            r.y = hv.y + 0.1f * (-hv.y * iv.y + fast_tanh(tv.y + cv.y));
            r.z = hv.z + 0.1f * (-hv.z * iv.z + fast_tanh(tv.z + cv.z));
            r.w = hv.w + 0.1f * (-hv.w * iv.w + fast_tanh(tv.w + cv.w));
            *reinterpret_cast<float4*>(&sH[row * H_ST + c4]) = r;
        }
        __syncthreads();
        {
            const int eg = (tid & 15) * 4;
            const int rb = tid >> 4;
            float4 acc0 = make_float4(0.f, 0.f, 0.f, 0.f);
            float4 acc1 = make_float4(0.f, 0.f, 0.f, 0.f);
            const float* h0 = sH + rb * H_ST;
            const float* h1 = sH + (rb + 16) * H_ST;
#pragma unroll 8
            for (int k = 0; k < RDIM; k++) {
                float4 w = __ldg(reinterpret_cast<const float4*>(Wg + k * 64 + eg));
                float a = h0[k], b = h1[k];
                acc0.x = fmaf(a, w.x, acc0.x); acc0.y = fmaf(a, w.y, acc0.y);
                acc0.z = fmaf(a, w.z, acc0.z); acc0.w = fmaf(a, w.w, acc0.w);
                acc1.x = fmaf(b, w.x, acc1.x); acc1.y = fmaf(b, w.y, acc1.y);
                acc1.z = fmaf(b, w.z, acc1.z); acc1.w = fmaf(b, w.w, acc1.w);
            }
            float4 bgv = *reinterpret_cast<const float4*>(bg + eg);
            acc0.x += bgv.x; acc0.y += bgv.y; acc0.z += bgv.z; acc0.w += bgv.w;
            acc1.x += bgv.x; acc1.y += bgv.y; acc1.z += bgv.z; acc1.w += bgv.w;
            *reinterpret_cast<float4*>(&sL[rb * 64 + eg]) = acc0;
            *reinterpret_cast<float4*>(&sL[(rb + 16) * 64 + eg]) = acc1;
        }
        __syncthreads();
        if (tid < 32) {
            int row = tid;
            size_t orow = r0 + row;
            int p0 = prev_sel[orow * 2 + 0];
            int p1 = prev_sel[orow * 2 + 1];
            float v1 = -1e30f, v2 = -1e30f, v3 = -1e30f;
            int i1 = 0, i2 = 0;
#pragma unroll
            for (int q = 0; q < 64; q++) {
                float v = sL[row * 64 + q] + ((q == p0 || q == p1) ? 0.1f : 0.f);
                if (v > v1)      { v3 = v2; v2 = v1; i2 = i1; v1 = v; i1 = q; }
                else if (v > v2) { v3 = v2; v2 = v; i2 = q; }
                else if (v > v3) { v3 = v; }
            }
            float gap = fminf(v1 - v2, v2 - v3);
            if (gap < THR) {
                int slot = atomicAdd(&g_cnt, 1);
                if (slot < BATCH) g_rows[slot] = (int)orow;
            }
            float e2 = expf(v2 - v1);
            float sm = 1.f + e2;
            out[orow * 2 + 0] = (float)i1;
            out[orow * 2 + 1] = (float)i2;
            size_t woff = (size_t)2 * B;
            out[woff + orow * 2 + 0] = 1.f / sm;
            out[woff + orow * 2 + 1] = e2 / sm;
        }
    }
}

// ===========================================================================
// Prep: g_W fp32 + g_Wth fp16 transposed; g_c; g_invtau; zero g_cnt/g_flag.
// Bm k-loop: unroll 8 + __ldg for deeper MLP (same per-output FMA order ->
// g_W/g_c bitwise identical to prior rounds).
// ===========================================================================
__global__ __launch_bounds__(256)
void k_prep(const float* __restrict__ Wp, const float* __restrict__ Bm,
            const float* __restrict__ A, const float* __restrict__ bp,
            const float* __restrict__ tau)
{
    __shared__ float sW16[16][257];
    const int tid = threadIdx.x;
    const int kb = blockIdx.x * 16;
    if (blockIdx.x == 0 && tid == 0) g_cnt = 0;
    if (blockIdx.x < NMBLK / 256) g_flag[blockIdx.x * 256 + tid] = 0;

    float vals[16];
    if (kb < RDIM) {
#pragma unroll
        for (int r = 0; r < 16; r++) {
            vals[r] = A[(size_t)(kb + r) * RDIM + tid];
            g_W[(size_t)(kb + r) * RDIM + tid] = vals[r];
        }
    } else {
        const int i0 = kb - RDIM;
#pragma unroll
        for (int r = 0; r < 16; r++)
            sW16[r][tid] = Wp[(size_t)(i0 + r) * RDIM + tid];
        __syncthreads();
#pragma unroll
        for (int r = 0; r < 16; r++) vals[r] = 0.f;
#pragma unroll 8
        for (int k = 0; k < RDIM; k++) {
            float bmv = __ldg(Bm + k * RDIM + tid);
#pragma unroll
            for (int r = 0; r < 16; r++)
                vals[r] = fmaf(sW16[r][k], bmv, vals[r]);
        }
#pragma unroll
        for (int r = 0; r < 16; r++)
            g_W[(size_t)(kb + r) * RDIM + tid] = vals[r];
    }

    {
        uint32_t p[8];
#pragma unroll
        for (int j = 0; j < 8; j++) {
            uint32_t r;
            asm("cvt.rn.f16x2.f32 %0, %1, %2;" : "=r"(r)
                : "f"(vals[2 * j + 1]), "f"(vals[2 * j]));
            p[j] = r;
        }
        uint4* dst = reinterpret_cast<uint4*>(
            reinterpret_cast<char*>(g_Wth) + ((size_t)tid * KTOT + kb) * 2);
        dst[0] = make_uint4(p[0], p[1], p[2], p[3]);
        dst[1] = make_uint4(p[4], p[5], p[6], p[7]);
    }

    if (blockIdx.x == 0) {
        float c = 0.f;
#pragma unroll 8
        for (int k = 0; k < RDIM; k++)
            c = fmaf(bp[k], __ldg(Bm + k * RDIM + tid), c);
        g_c[tid] = c;
        g_invtau[tid] = 1.f / tau[tid];
    }
}

// ===========================================================================
// Fixup GEMM, split-K (measured-best geometry): 64 rows/block x 16 K-splits.
// Exact fp32 partials for flagged rows into g_part (deterministic).
// ===========================================================================
__global__ __launch_bounds__(256)
void k_fixT(const float* __restrict__ h, const float* __restrict__ x,
            const float* __restrict__ W)
{
    int nrows = g_cnt; if (nrows > MAXFIX) nrows = MAXFIX;
    const int m0 = blockIdx.x * 64;
    if (m0 >= nrows) return;
    const int ks = blockIdx.y;
    const int kbase = ks * KCHUNK;

    __shared__ float sX[64][16];
    __shared__ float sW[16][256];
    __shared__ int   srows[64];

    const int tid = threadIdx.x;
    const int tx = tid & 31, ty = tid >> 5;
    const int xr = tid >> 2, xq = tid & 3;
    const int wr = tid >> 6, wc = tid & 63;

    if (tid < 64) {
        int idx = m0 + tid;
        srows[tid] = g_rows[idx < nrows ? idx : nrows - 1];
    }
    __syncthreads();

    float acc[8][8];
#pragma unroll
    for (int i = 0; i < 8; i++)
#pragma unroll
        for (int j = 0; j < 8; j++) acc[i][j] = 0.f;

    for (int k0 = kbase; k0 < kbase + KCHUNK; k0 += 16) {
        {
            int row = srows[xr];
            int kg = k0 + xq * 4;
            const float* src = (kg < RDIM)
                ? (h + (size_t)row * RDIM + kg)
                : (x + (size_t)row * HID + (kg - RDIM));
            *reinterpret_cast<float4*>(&sX[xr][xq * 4]) =
                *reinterpret_cast<const float4*>(src);
        }
#pragma unroll
        for (int r = 0; r < 4; r++)
            *reinterpret_cast<float4*>(&sW[wr + 4 * r][wc * 4]) =
                *reinterpret_cast<const float4*>(W + (size_t)(k0 + wr + 4 * r) * 256 + wc * 4);
        __syncthreads();

#pragma unroll
        for (int k = 0; k < 16; k++) {
            float a[8], b[8];
#pragma unroll
            for (int i = 0; i < 8; i++) a[i] = sX[ty + 8 * i][k];
#pragma unroll
            for (int j = 0; j < 8; j++) b[j] = sW[k][tx + 32 * j];
#pragma unroll
            for (int i = 0; i < 8; i++)
#pragma unroll
                for (int j = 0; j < 8; j++)
                    acc[i][j] = fmaf(a[i], b[j], acc[i][j]);
        }
        __syncthreads();
    }

#pragma unroll
    for (int i = 0; i < 8; i++) {
        int rl = ty + 8 * i;
        if (m0 + rl < nrows) {
            float* dst = &g_part[((size_t)(m0 + rl) * KSPL + ks) * RDIM];
#pragma unroll
            for (int j = 0; j < 8; j++)
                dst[tx + 32 * j] = acc[i][j];
        }
    }
}

// ===========================================================================
// Fixup epilogue: reduce K-split partials, exact recompute, overwrite.
// ===========================================================================
__global__ __launch_bounds__(256)
void k_fixEpi(const float* __restrict__ h, const int* __restrict__ prev_sel,
              const float* __restrict__ tau, const float* __restrict__ Wg,
              const float* __restrict__ bg, float* __restrict__ out, int B)
{
    __shared__ float sH[RDIM];
    __shared__ float sPart[4][EDIM];
    __shared__ float sL[EDIM];
    const int j = threadIdx.x;
    int n = g_cnt; if (n > MAXFIX) n = MAXFIX;

    for (int r = blockIdx.x; r < n; r += gridDim.x) {
        size_t row = (size_t)g_rows[r];
        float Tj = 0.f;
#pragma unroll
        for (int ks = 0; ks < KSPL; ks++)
            Tj += g_part[((size_t)r * KSPL + ks) * RDIM + j];
        float hj = h[row * 256 + j];
        sH[j] = hj + 0.1f * (-hj / tau[j] + tanhf(Tj + g_c[j]));
        __syncthreads();

        int e = j & 63, p = j >> 6;
        float acc = 0.f;
#pragma unroll 8
        for (int k = p * 64; k < p * 64 + 64; k++)
            acc = fmaf(sH[k], Wg[k * EDIM + e], acc);
        sPart[p][e] = acc;
        __syncthreads();

        if (j < EDIM) {
            float lg = sPart[0][j] + sPart[1][j] + sPart[2][j] + sPart[3][j] + bg[j];
            int p0 = prev_sel[row * 2 + 0];
            int p1 = prev_sel[row * 2 + 1];
            if (j == p0 || j == p1) lg += 0.1f;
            sL[j] = lg;
        }
        __syncthreads();

        if (j == 0) {
            float v1 = -1e30f, v2 = -1e30f;
            int i1 = 0, i2 = 0;
#pragma unroll
            for (int q = 0; q < 64; q++) {
                float v = sL[q];
                if (v > v1) { v2 = v1; i2 = i1; v1 = v; i1 = q; }
                else if (v > v2) { v2 = v; i2 = q; }
            }
            float e2 = expf(v2 - v1);
            float sm = 1.f + e2;
            out[row * 2 + 0] = (float)i1;
            out[row * 2 + 1] = (float)i2;
            size_t woff = (size_t)2 * B;
            out[woff + row * 2 + 0] = 1.f / sm;
            out[woff + row * 2 + 1] = e2 / sm;
        }
        __syncthreads();
    }
}

// ===========================================================================
extern "C" void kernel_launch(void* const* d_in, const int* in_sizes, int n_in,
                              void* d_out, int out_size)
{
    const float *x = 0, *h = 0, *Wp = 0, *bp = 0, *tau = 0, *A = 0, *Bm = 0,
                *Wg = 0, *bg = 0;
    const int* prev_sel = 0;
    for (int i = 0; i < n_in; i++) {
        int s = in_sizes[i];
        const void* pv = d_in[i];
        switch (s) {
            case BATCH * HID:  x = (const float*)pv; break;
            case BATCH * RDIM: h = (const float*)pv; break;
            case BATCH * TOPK: prev_sel = (const int*)pv; break;
            case HID * RDIM:   Wp = (const float*)pv; break;
            case RDIM:         if (!bp) bp = (const float*)pv; else tau = (const float*)pv; break;
            case RDIM * RDIM:  if (!A) A = (const float*)pv; else Bm = (const float*)pv; break;
            case RDIM * EDIM:  Wg = (const float*)pv; break;
            case EDIM:         bg = (const float*)pv; break;
            default: break;
        }
    }
    if (!x)        x        = (const float*)d_in[0];
    if (!h)        h        = (const float*)d_in[1];
    if (!prev_sel) prev_sel = (const int*)d_in[2];
    if (!Wp)       Wp       = (const float*)d_in[3];
    if (!bp)       bp       = (const float*)d_in[4];
    if (!tau)      tau      = (const float*)d_in[5];
    if (!A)        A        = (const float*)d_in[6];
    if (!Bm)       Bm       = (const float*)d_in[7];
    if (!Wg)       Wg       = (const float*)d_in[8];
    if (!bg)       bg       = (const float*)d_in[9];

    static int attr_done = 0;
    if (!attr_done) {
        cudaFuncSetAttribute(gemm_fused, cudaFuncAttributeMaxDynamicSharedMemorySize, SMEM_GEMM);
        attr_done = 1;
    }

    float  *Wptr = 0, *Tp = 0;
    __half *Wth = 0;
    cudaGetSymbolAddress((void**)&Wptr, g_W);
    cudaGetSymbolAddress((void**)&Wth, g_Wth);
    cudaGetSymbolAddress((void**)&Tp, g_T);
    float* out = (float*)d_out;

    // 1) weights + invtau + counters/flags (deeper-MLP Bm loop)
    k_prep<<<KTOT / 16, 256>>>(Wp, Bm, A, bp, tau);
    // 2) GEMM + fused epilogue (measured-best configuration)
    dim3 grid(BATCH / 128, 2);
    gemm_fused<<<grid, 256, SMEM_GEMM>>>(h, x, Wth, Tp, prev_sel, Wg, bg, out, BATCH);
    // 3) exact fp32 recompute of flagged rows (64 rows/block x 16 K-splits)
    dim3 fgrid(MAXFIX / 64, KSPL);
    k_fixT<<<fgrid, 256>>>(h, x, Wptr);
    k_fixEpi<<<2048, 256>>>(h, prev_sel, tau, Wg, bg, out, BATCH);
}